// round 2
// baseline (speedup 1.0000x reference)
#include <cuda_runtime.h>
#include <math.h>

// Problem constants
#define T_TOK 4096          // B*S tokens
#define H_DIM 1024
#define I_DIM 4096
#define E_EXP 8
#define K_TOP 2
#define P_PAIR (T_TOK * K_TOP)   // 8192 token-expert pairs

// ---------------- scratch (static device globals; no runtime alloc) ----------
__device__ float g_hdn[(size_t)P_PAIR * I_DIM];      // 134 MB: silu(g)*u per pair
__device__ float g_pairout[(size_t)P_PAIR * H_DIM];  // 33 MB: per-pair down-proj out
__device__ int   g_perm[P_PAIR];                      // pair -> token
__device__ float g_pairw[P_PAIR];                     // pair combine weight
__device__ int   g_pos[P_PAIR];                       // (token,k) -> pair slot
__device__ int   g_tki[T_TOK * K_TOP];
__device__ float g_tkw[T_TOK * K_TOP];
__device__ int   g_counts[E_EXP];
__device__ int   g_offsets[E_EXP];
__device__ int   g_cursor[E_EXP];
__device__ float g_load[E_EXP];

// ---------------- small kernels ----------------------------------------------
__global__ void zero_kernel() {
    int i = threadIdx.x;
    if (i < E_EXP) { g_counts[i] = 0; g_load[i] = 0.f; }
}

// One block (256 thr, 8 warps) per token. Warp w computes logit for expert w.
__global__ void router_kernel(const float* __restrict__ x,
                              const float* __restrict__ gw) {
    int t = blockIdx.x;
    int w = threadIdx.x >> 5, lane = threadIdx.x & 31;
    __shared__ float logits[E_EXP];
    const float* xr = x + (size_t)t * H_DIM;
    float s = 0.f;
    for (int h = lane; h < H_DIM; h += 32)
        s += xr[h] * gw[h * E_EXP + w];
    #pragma unroll
    for (int o = 16; o; o >>= 1) s += __shfl_xor_sync(0xffffffffu, s, o);
    if (lane == 0) logits[w] = s;
    __syncthreads();
    if (threadIdx.x == 0) {
        float mx = logits[0];
        #pragma unroll
        for (int e = 1; e < E_EXP; e++) mx = fmaxf(mx, logits[e]);
        float p[E_EXP], den = 0.f;
        #pragma unroll
        for (int e = 0; e < E_EXP; e++) { p[e] = expf(logits[e] - mx); den += p[e]; }
        #pragma unroll
        for (int e = 0; e < E_EXP; e++) p[e] /= den;
        // top-2 (earliest index wins ties, matching lax.top_k)
        int i0 = 0;
        #pragma unroll
        for (int e = 1; e < E_EXP; e++) if (p[e] > p[i0]) i0 = e;
        int i1 = -1;
        #pragma unroll
        for (int e = 0; e < E_EXP; e++) {
            if (e == i0) continue;
            if (i1 < 0 || p[e] > p[i1]) i1 = e;
        }
        float w0 = p[i0], w1 = p[i1], sm = w0 + w1;
        g_tki[t * 2 + 0] = i0; g_tki[t * 2 + 1] = i1;
        g_tkw[t * 2 + 0] = w0 / sm; g_tkw[t * 2 + 1] = w1 / sm;
        atomicAdd(&g_counts[i0], 1); atomicAdd(&g_counts[i1], 1);
        atomicAdd(&g_load[i0], w0);  atomicAdd(&g_load[i1], w1);
    }
}

__global__ void finalize_router(float* out_aux, int write_aux) {
    if (threadIdx.x == 0) {
        int off = 0;
        for (int e = 0; e < E_EXP; e++) {
            g_offsets[e] = off; g_cursor[e] = off; off += g_counts[e];
        }
        if (write_aux) {
            float aux = 0.f;
            for (int e = 0; e < E_EXP; e++) {
                float Pe = g_load[e] / (float)T_TOK;
                float Pt = (float)g_counts[e] / (float)(T_TOK * K_TOP);
                aux += Pe * Pt;
            }
            *out_aux = aux * (float)E_EXP * 0.001f;
        }
    }
}

__global__ void scatter_kernel() {
    int t = blockIdx.x * blockDim.x + threadIdx.x;
    if (t >= T_TOK) return;
    #pragma unroll
    for (int k = 0; k < K_TOP; k++) {
        int e = g_tki[t * 2 + k];
        int p = atomicAdd(&g_cursor[e], 1);
        g_perm[p] = t;
        g_pairw[p] = g_tkw[t * 2 + k];
        g_pos[t * 2 + k] = p;
    }
}

// ---------------- grouped GEMM 1: hdn = silu(X@wg[e]) * (X@wu[e]) ------------
// 64x64 tile of both G and U, TK=16, 256 threads, 4x4 micro-tile each.
__global__ void __launch_bounds__(256) ffn1_kernel(
    const float* __restrict__ x,
    const float* __restrict__ wg,
    const float* __restrict__ wu) {
    const int e = blockIdx.z;
    const int cnt = g_counts[e];
    const int m0 = blockIdx.y * 64;
    if (m0 >= cnt) return;
    const int beg = g_offsets[e];
    const int n0 = blockIdx.x * 64;

    __shared__ float As[16][64];
    __shared__ float Bg[16][64];
    __shared__ float Bu[16][64];
    __shared__ int perm_s[64];

    const int tid = threadIdx.x;
    if (tid < 64) {
        int r = m0 + tid;
        perm_s[tid] = (r < cnt) ? g_perm[beg + r] : -1;
    }
    __syncthreads();

    const int tx = tid & 15, ty = tid >> 4;   // 16x16 threads
    float accG[4][4] = {}, accU[4][4] = {};
    const float* wgb = wg + (size_t)e * H_DIM * I_DIM;
    const float* wub = wu + (size_t)e * H_DIM * I_DIM;

    // A-load mapping: thread covers 4 consecutive k of one m
    const int a_m  = tid >> 2;          // 0..63
    const int a_k  = (tid & 3) * 4;     // 0,4,8,12
    // B-load mapping: thread covers 4 consecutive n of one k
    const int b_k  = tid >> 4;          // 0..15
    const int b_n  = (tid & 15) * 4;    // 0..60

    for (int k0 = 0; k0 < H_DIM; k0 += 16) {
        // load A (64x16), gathered rows
        {
            int pm = perm_s[a_m];
            float4 v = make_float4(0.f, 0.f, 0.f, 0.f);
            if (pm >= 0)
                v = *(const float4*)(x + (size_t)pm * H_DIM + k0 + a_k);
            As[a_k + 0][a_m] = v.x; As[a_k + 1][a_m] = v.y;
            As[a_k + 2][a_m] = v.z; As[a_k + 3][a_m] = v.w;
        }
        // load Bg, Bu (16x64)
        {
            size_t bo = (size_t)(k0 + b_k) * I_DIM + n0 + b_n;
            *(float4*)&Bg[b_k][b_n] = *(const float4*)(wgb + bo);
            *(float4*)&Bu[b_k][b_n] = *(const float4*)(wub + bo);
        }
        __syncthreads();
        #pragma unroll
        for (int kk = 0; kk < 16; kk++) {
            float a[4], bg[4], bu[4];
            #pragma unroll
            for (int i = 0; i < 4; i++) a[i] = As[kk][ty * 4 + i];
            #pragma unroll
            for (int j = 0; j < 4; j++) { bg[j] = Bg[kk][tx * 4 + j]; bu[j] = Bu[kk][tx * 4 + j]; }
            #pragma unroll
            for (int i = 0; i < 4; i++)
                #pragma unroll
                for (int j = 0; j < 4; j++) {
                    accG[i][j] = fmaf(a[i], bg[j], accG[i][j]);
                    accU[i][j] = fmaf(a[i], bu[j], accU[i][j]);
                }
        }
        __syncthreads();
    }
    // epilogue: silu(g)*u -> g_hdn
    #pragma unroll
    for (int i = 0; i < 4; i++) {
        int r = m0 + ty * 4 + i;
        if (r >= cnt) continue;
        size_t base = (size_t)(beg + r) * I_DIM + n0 + tx * 4;
        #pragma unroll
        for (int j = 0; j < 4; j++) {
            float g = accG[i][j], u = accU[i][j];
            float s = g / (1.f + expf(-g));
            g_hdn[base + j] = s * u;
        }
    }
}

// ---------------- grouped GEMM 2: pairout = (hdn @ wd[e]) * pairw ------------
__global__ void __launch_bounds__(256) ffn2_kernel(const float* __restrict__ wd) {
    const int e = blockIdx.z;
    const int cnt = g_counts[e];
    const int m0 = blockIdx.y * 64;
    if (m0 >= cnt) return;
    const int beg = g_offsets[e];
    const int n0 = blockIdx.x * 64;

    __shared__ float As[16][64];
    __shared__ float Bs[16][64];

    const int tid = threadIdx.x;
    const int tx = tid & 15, ty = tid >> 4;
    float acc[4][4] = {};
    const float* wdb = wd + (size_t)e * I_DIM * H_DIM;

    const int a_m = tid >> 2;
    const int a_k = (tid & 3) * 4;
    const int b_k = tid >> 4;
    const int b_n = (tid & 15) * 4;

    for (int k0 = 0; k0 < I_DIM; k0 += 16) {
        {
            int r = m0 + a_m;
            float4 v = make_float4(0.f, 0.f, 0.f, 0.f);
            if (r < cnt)
                v = *(const float4*)(g_hdn + (size_t)(beg + r) * I_DIM + k0 + a_k);
            As[a_k + 0][a_m] = v.x; As[a_k + 1][a_m] = v.y;
            As[a_k + 2][a_m] = v.z; As[a_k + 3][a_m] = v.w;
        }
        {
            size_t bo = (size_t)(k0 + b_k) * H_DIM + n0 + b_n;
            *(float4*)&Bs[b_k][b_n] = *(const float4*)(wdb + bo);
        }
        __syncthreads();
        #pragma unroll
        for (int kk = 0; kk < 16; kk++) {
            float a[4], b[4];
            #pragma unroll
            for (int i = 0; i < 4; i++) a[i] = As[kk][ty * 4 + i];
            #pragma unroll
            for (int j = 0; j < 4; j++) b[j] = Bs[kk][tx * 4 + j];
            #pragma unroll
            for (int i = 0; i < 4; i++)
                #pragma unroll
                for (int j = 0; j < 4; j++)
                    acc[i][j] = fmaf(a[i], b[j], acc[i][j]);
        }
        __syncthreads();
    }
    #pragma unroll
    for (int i = 0; i < 4; i++) {
        int r = m0 + ty * 4 + i;
        if (r >= cnt) continue;
        float pw = g_pairw[beg + r];
        size_t base = (size_t)(beg + r) * H_DIM + n0 + tx * 4;
        #pragma unroll
        for (int j = 0; j < 4; j++)
            g_pairout[base + j] = acc[i][j] * pw;
    }
}

// ---------------- combine: out[t] = pairout[pos0] + pairout[pos1] ------------
__global__ void combine_kernel(float* __restrict__ out) {
    int idx = blockIdx.x * blockDim.x + threadIdx.x;
    if (idx >= T_TOK * H_DIM) return;
    int t = idx >> 10;          // /H_DIM
    int h = idx & (H_DIM - 1);
    int p0 = g_pos[t * 2 + 0], p1 = g_pos[t * 2 + 1];
    out[idx] = g_pairout[(size_t)p0 * H_DIM + h] + g_pairout[(size_t)p1 * H_DIM + h];
}

// ---------------- launcher ----------------------------------------------------
extern "C" void kernel_launch(void* const* d_in, const int* in_sizes, int n_in,
                              void* d_out, int out_size) {
    const float* x  = (const float*)d_in[0];
    const float* gw = (const float*)d_in[1];
    const float* wg = (const float*)d_in[2];
    const float* wu = (const float*)d_in[3];
    const float* wd = (const float*)d_in[4];
    float* out = (float*)d_out;

    zero_kernel<<<1, 32>>>();
    router_kernel<<<T_TOK, 256>>>(x, gw);
    int write_aux = (out_size > T_TOK * H_DIM) ? 1 : 0;
    finalize_router<<<1, 1>>>(out + (size_t)T_TOK * H_DIM, write_aux);
    scatter_kernel<<<(T_TOK + 255) / 256, 256>>>();

    dim3 g1(I_DIM / 64, T_TOK / 64, E_EXP);
    ffn1_kernel<<<g1, 256>>>(x, wg, wu);
    dim3 g2(H_DIM / 64, T_TOK / 64, E_EXP);
    ffn2_kernel<<<g2, 256>>>(wd);

    combine_kernel<<<(T_TOK * H_DIM + 255) / 256, 256>>>(out);
}

// round 3
// speedup vs baseline: 1.0007x; 1.0007x over previous
#include <cuda_runtime.h>
#include <math.h>

// Problem constants
#define T_TOK 4096          // B*S tokens
#define H_DIM 1024
#define I_DIM 4096
#define E_EXP 8
#define K_TOP 2
#define P_PAIR (T_TOK * K_TOP)   // 8192 token-expert pairs

// ---------------- scratch (static device globals; no runtime alloc) ----------
__device__ float g_hdn[(size_t)P_PAIR * I_DIM];      // 134 MB: silu(g)*u per pair
__device__ float g_pairout[(size_t)P_PAIR * H_DIM];  // 33 MB: per-pair down-proj out
__device__ int   g_perm[P_PAIR];                      // pair -> token
__device__ float g_pairw[P_PAIR];                     // pair combine weight
__device__ int   g_pos[P_PAIR];                       // (token,k) -> pair slot
__device__ int   g_tki[T_TOK * K_TOP];
__device__ float g_tkw[T_TOK * K_TOP];
__device__ int   g_counts[E_EXP];
__device__ int   g_offsets[E_EXP];
__device__ int   g_cursor[E_EXP];
__device__ float g_load[E_EXP];

// ---------------- small kernels ----------------------------------------------
__global__ void zero_kernel() {
    int i = threadIdx.x;
    if (i < E_EXP) { g_counts[i] = 0; g_load[i] = 0.f; }
}

// One block (256 thr, 8 warps) per token. Warp w computes logit for expert w.
__global__ void router_kernel(const float* __restrict__ x,
                              const float* __restrict__ gw) {
    int t = blockIdx.x;
    int w = threadIdx.x >> 5, lane = threadIdx.x & 31;
    __shared__ float logits[E_EXP];
    const float* xr = x + (size_t)t * H_DIM;
    float s = 0.f;
    for (int h = lane; h < H_DIM; h += 32)
        s += xr[h] * gw[h * E_EXP + w];
    #pragma unroll
    for (int o = 16; o; o >>= 1) s += __shfl_xor_sync(0xffffffffu, s, o);
    if (lane == 0) logits[w] = s;
    __syncthreads();
    if (threadIdx.x == 0) {
        float mx = logits[0];
        #pragma unroll
        for (int e = 1; e < E_EXP; e++) mx = fmaxf(mx, logits[e]);
        float p[E_EXP], den = 0.f;
        #pragma unroll
        for (int e = 0; e < E_EXP; e++) { p[e] = expf(logits[e] - mx); den += p[e]; }
        #pragma unroll
        for (int e = 0; e < E_EXP; e++) p[e] /= den;
        // top-2 (earliest index wins ties, matching lax.top_k)
        int i0 = 0;
        #pragma unroll
        for (int e = 1; e < E_EXP; e++) if (p[e] > p[i0]) i0 = e;
        int i1 = -1;
        #pragma unroll
        for (int e = 0; e < E_EXP; e++) {
            if (e == i0) continue;
            if (i1 < 0 || p[e] > p[i1]) i1 = e;
        }
        float w0 = p[i0], w1 = p[i1], sm = w0 + w1;
        g_tki[t * 2 + 0] = i0; g_tki[t * 2 + 1] = i1;
        g_tkw[t * 2 + 0] = w0 / sm; g_tkw[t * 2 + 1] = w1 / sm;
        atomicAdd(&g_counts[i0], 1); atomicAdd(&g_counts[i1], 1);
        atomicAdd(&g_load[i0], w0);  atomicAdd(&g_load[i1], w1);
    }
}

__global__ void finalize_router(float* out_aux, int write_aux) {
    if (threadIdx.x == 0) {
        int off = 0;
        for (int e = 0; e < E_EXP; e++) {
            g_offsets[e] = off; g_cursor[e] = off; off += g_counts[e];
        }
        if (write_aux) {
            float aux = 0.f;
            for (int e = 0; e < E_EXP; e++) {
                float Pe = g_load[e] / (float)T_TOK;
                float Pt = (float)g_counts[e] / (float)(T_TOK * K_TOP);
                aux += Pe * Pt;
            }
            *out_aux = aux * (float)E_EXP * 0.001f;
        }
    }
}

__global__ void scatter_kernel() {
    int t = blockIdx.x * blockDim.x + threadIdx.x;
    if (t >= T_TOK) return;
    #pragma unroll
    for (int k = 0; k < K_TOP; k++) {
        int e = g_tki[t * 2 + k];
        int p = atomicAdd(&g_cursor[e], 1);
        g_perm[p] = t;
        g_pairw[p] = g_tkw[t * 2 + k];
        g_pos[t * 2 + k] = p;
    }
}

// ---------------- grouped GEMM 1: hdn = silu(X@wg[e]) * (X@wu[e]) ------------
// 64x64 tile of both G and U, TK=16, 256 threads, 4x4 micro-tile each.
__global__ void __launch_bounds__(256) ffn1_kernel(
    const float* __restrict__ x,
    const float* __restrict__ wg,
    const float* __restrict__ wu) {
    const int e = blockIdx.z;
    const int cnt = g_counts[e];
    const int m0 = blockIdx.y * 64;
    if (m0 >= cnt) return;
    const int beg = g_offsets[e];
    const int n0 = blockIdx.x * 64;

    __shared__ float As[16][64];
    __shared__ float Bg[16][64];
    __shared__ float Bu[16][64];
    __shared__ int perm_s[64];

    const int tid = threadIdx.x;
    if (tid < 64) {
        int r = m0 + tid;
        perm_s[tid] = (r < cnt) ? g_perm[beg + r] : -1;
    }
    __syncthreads();

    const int tx = tid & 15, ty = tid >> 4;   // 16x16 threads
    float accG[4][4] = {}, accU[4][4] = {};
    const float* wgb = wg + (size_t)e * H_DIM * I_DIM;
    const float* wub = wu + (size_t)e * H_DIM * I_DIM;

    // A-load mapping: thread covers 4 consecutive k of one m
    const int a_m  = tid >> 2;          // 0..63
    const int a_k  = (tid & 3) * 4;     // 0,4,8,12
    // B-load mapping: thread covers 4 consecutive n of one k
    const int b_k  = tid >> 4;          // 0..15
    const int b_n  = (tid & 15) * 4;    // 0..60

    for (int k0 = 0; k0 < H_DIM; k0 += 16) {
        // load A (64x16), gathered rows
        {
            int pm = perm_s[a_m];
            float4 v = make_float4(0.f, 0.f, 0.f, 0.f);
            if (pm >= 0)
                v = *(const float4*)(x + (size_t)pm * H_DIM + k0 + a_k);
            As[a_k + 0][a_m] = v.x; As[a_k + 1][a_m] = v.y;
            As[a_k + 2][a_m] = v.z; As[a_k + 3][a_m] = v.w;
        }
        // load Bg, Bu (16x64)
        {
            size_t bo = (size_t)(k0 + b_k) * I_DIM + n0 + b_n;
            *(float4*)&Bg[b_k][b_n] = *(const float4*)(wgb + bo);
            *(float4*)&Bu[b_k][b_n] = *(const float4*)(wub + bo);
        }
        __syncthreads();
        #pragma unroll
        for (int kk = 0; kk < 16; kk++) {
            float a[4], bg[4], bu[4];
            #pragma unroll
            for (int i = 0; i < 4; i++) a[i] = As[kk][ty * 4 + i];
            #pragma unroll
            for (int j = 0; j < 4; j++) { bg[j] = Bg[kk][tx * 4 + j]; bu[j] = Bu[kk][tx * 4 + j]; }
            #pragma unroll
            for (int i = 0; i < 4; i++)
                #pragma unroll
                for (int j = 0; j < 4; j++) {
                    accG[i][j] = fmaf(a[i], bg[j], accG[i][j]);
                    accU[i][j] = fmaf(a[i], bu[j], accU[i][j]);
                }
        }
        __syncthreads();
    }
    // epilogue: silu(g)*u -> g_hdn
    #pragma unroll
    for (int i = 0; i < 4; i++) {
        int r = m0 + ty * 4 + i;
        if (r >= cnt) continue;
        size_t base = (size_t)(beg + r) * I_DIM + n0 + tx * 4;
        #pragma unroll
        for (int j = 0; j < 4; j++) {
            float g = accG[i][j], u = accU[i][j];
            float s = g / (1.f + expf(-g));
            g_hdn[base + j] = s * u;
        }
    }
}

// ---------------- grouped GEMM 2: pairout = (hdn @ wd[e]) * pairw ------------
__global__ void __launch_bounds__(256) ffn2_kernel(const float* __restrict__ wd) {
    const int e = blockIdx.z;
    const int cnt = g_counts[e];
    const int m0 = blockIdx.y * 64;
    if (m0 >= cnt) return;
    const int beg = g_offsets[e];
    const int n0 = blockIdx.x * 64;

    __shared__ float As[16][64];
    __shared__ float Bs[16][64];

    const int tid = threadIdx.x;
    const int tx = tid & 15, ty = tid >> 4;
    float acc[4][4] = {};
    const float* wdb = wd + (size_t)e * I_DIM * H_DIM;

    const int a_m = tid >> 2;
    const int a_k = (tid & 3) * 4;
    const int b_k = tid >> 4;
    const int b_n = (tid & 15) * 4;

    for (int k0 = 0; k0 < I_DIM; k0 += 16) {
        {
            int r = m0 + a_m;
            float4 v = make_float4(0.f, 0.f, 0.f, 0.f);
            if (r < cnt)
                v = *(const float4*)(g_hdn + (size_t)(beg + r) * I_DIM + k0 + a_k);
            As[a_k + 0][a_m] = v.x; As[a_k + 1][a_m] = v.y;
            As[a_k + 2][a_m] = v.z; As[a_k + 3][a_m] = v.w;
        }
        {
            size_t bo = (size_t)(k0 + b_k) * H_DIM + n0 + b_n;
            *(float4*)&Bs[b_k][b_n] = *(const float4*)(wdb + bo);
        }
        __syncthreads();
        #pragma unroll
        for (int kk = 0; kk < 16; kk++) {
            float a[4], b[4];
            #pragma unroll
            for (int i = 0; i < 4; i++) a[i] = As[kk][ty * 4 + i];
            #pragma unroll
            for (int j = 0; j < 4; j++) b[j] = Bs[kk][tx * 4 + j];
            #pragma unroll
            for (int i = 0; i < 4; i++)
                #pragma unroll
                for (int j = 0; j < 4; j++)
                    acc[i][j] = fmaf(a[i], b[j], acc[i][j]);
        }
        __syncthreads();
    }
    #pragma unroll
    for (int i = 0; i < 4; i++) {
        int r = m0 + ty * 4 + i;
        if (r >= cnt) continue;
        float pw = g_pairw[beg + r];
        size_t base = (size_t)(beg + r) * H_DIM + n0 + tx * 4;
        #pragma unroll
        for (int j = 0; j < 4; j++)
            g_pairout[base + j] = acc[i][j] * pw;
    }
}

// ---------------- combine: out[t] = pairout[pos0] + pairout[pos1] ------------
__global__ void combine_kernel(float* __restrict__ out) {
    int idx = blockIdx.x * blockDim.x + threadIdx.x;
    if (idx >= T_TOK * H_DIM) return;
    int t = idx >> 10;          // /H_DIM
    int h = idx & (H_DIM - 1);
    int p0 = g_pos[t * 2 + 0], p1 = g_pos[t * 2 + 1];
    out[idx] = g_pairout[(size_t)p0 * H_DIM + h] + g_pairout[(size_t)p1 * H_DIM + h];
}

// ---------------- launcher ----------------------------------------------------
extern "C" void kernel_launch(void* const* d_in, const int* in_sizes, int n_in,
                              void* d_out, int out_size) {
    const float* x  = (const float*)d_in[0];
    const float* gw = (const float*)d_in[1];
    const float* wg = (const float*)d_in[2];
    const float* wu = (const float*)d_in[3];
    const float* wd = (const float*)d_in[4];
    float* out = (float*)d_out;

    zero_kernel<<<1, 32>>>();
    router_kernel<<<T_TOK, 256>>>(x, gw);
    int write_aux = (out_size > T_TOK * H_DIM) ? 1 : 0;
    finalize_router<<<1, 1>>>(out + (size_t)T_TOK * H_DIM, write_aux);
    scatter_kernel<<<(T_TOK + 255) / 256, 256>>>();

    dim3 g1(I_DIM / 64, T_TOK / 64, E_EXP);
    ffn1_kernel<<<g1, 256>>>(x, wg, wu);
    dim3 g2(H_DIM / 64, T_TOK / 64, E_EXP);
    ffn2_kernel<<<g2, 256>>>(wd);

    combine_kernel<<<(T_TOK * H_DIM + 255) / 256, 256>>>(out);
}

// round 4
// speedup vs baseline: 1.3981x; 1.3971x over previous
#include <cuda_runtime.h>
#include <math.h>

// Problem constants
#define T_TOK 4096          // B*S tokens
#define H_DIM 1024
#define I_DIM 4096
#define E_EXP 8
#define K_TOP 2
#define P_PAIR (T_TOK * K_TOP)   // 8192 token-expert pairs

// ---------------- scratch (static device globals; no runtime alloc) ----------
__device__ float g_hdn[(size_t)P_PAIR * I_DIM];      // silu(g)*u per pair
__device__ float g_pairout[(size_t)P_PAIR * H_DIM];  // per-pair down-proj out
__device__ int   g_perm[P_PAIR];
__device__ float g_pairw[P_PAIR];
__device__ int   g_pos[P_PAIR];
__device__ int   g_tki[T_TOK * K_TOP];
__device__ float g_tkw[T_TOK * K_TOP];
__device__ int   g_counts[E_EXP];
__device__ int   g_offsets[E_EXP];
__device__ int   g_cursor[E_EXP];
__device__ float g_load[E_EXP];

// ---------------- small kernels ----------------------------------------------
__global__ void zero_kernel() {
    int i = threadIdx.x;
    if (i < E_EXP) { g_counts[i] = 0; g_load[i] = 0.f; }
}

__global__ void router_kernel(const float* __restrict__ x,
                              const float* __restrict__ gw) {
    int t = blockIdx.x;
    int w = threadIdx.x >> 5, lane = threadIdx.x & 31;
    __shared__ float logits[E_EXP];
    const float* xr = x + (size_t)t * H_DIM;
    float s = 0.f;
    for (int h = lane; h < H_DIM; h += 32)
        s += xr[h] * gw[h * E_EXP + w];
    #pragma unroll
    for (int o = 16; o; o >>= 1) s += __shfl_xor_sync(0xffffffffu, s, o);
    if (lane == 0) logits[w] = s;
    __syncthreads();
    if (threadIdx.x == 0) {
        float mx = logits[0];
        #pragma unroll
        for (int e = 1; e < E_EXP; e++) mx = fmaxf(mx, logits[e]);
        float p[E_EXP], den = 0.f;
        #pragma unroll
        for (int e = 0; e < E_EXP; e++) { p[e] = expf(logits[e] - mx); den += p[e]; }
        #pragma unroll
        for (int e = 0; e < E_EXP; e++) p[e] /= den;
        int i0 = 0;
        #pragma unroll
        for (int e = 1; e < E_EXP; e++) if (p[e] > p[i0]) i0 = e;
        int i1 = -1;
        #pragma unroll
        for (int e = 0; e < E_EXP; e++) {
            if (e == i0) continue;
            if (i1 < 0 || p[e] > p[i1]) i1 = e;
        }
        float w0 = p[i0], w1 = p[i1], sm = w0 + w1;
        g_tki[t * 2 + 0] = i0; g_tki[t * 2 + 1] = i1;
        g_tkw[t * 2 + 0] = w0 / sm; g_tkw[t * 2 + 1] = w1 / sm;
        atomicAdd(&g_counts[i0], 1); atomicAdd(&g_counts[i1], 1);
        atomicAdd(&g_load[i0], w0);  atomicAdd(&g_load[i1], w1);
    }
}

__global__ void finalize_router(float* out_aux, int write_aux) {
    if (threadIdx.x == 0) {
        int off = 0;
        for (int e = 0; e < E_EXP; e++) {
            g_offsets[e] = off; g_cursor[e] = off; off += g_counts[e];
        }
        if (write_aux) {
            float aux = 0.f;
            for (int e = 0; e < E_EXP; e++) {
                float Pe = g_load[e] / (float)T_TOK;
                float Pt = (float)g_counts[e] / (float)(T_TOK * K_TOP);
                aux += Pe * Pt;
            }
            *out_aux = aux * (float)E_EXP * 0.001f;
        }
    }
}

__global__ void scatter_kernel() {
    int t = blockIdx.x * blockDim.x + threadIdx.x;
    if (t >= T_TOK) return;
    #pragma unroll
    for (int k = 0; k < K_TOP; k++) {
        int e = g_tki[t * 2 + k];
        int p = atomicAdd(&g_cursor[e], 1);
        g_perm[p] = t;
        g_pairw[p] = g_tkw[t * 2 + k];
        g_pos[t * 2 + k] = p;
    }
}

// ---------------- tf32 helpers ------------------------------------------------
__device__ __forceinline__ unsigned cvt_tf32(float x) {
    unsigned u; asm("cvt.rna.tf32.f32 %0, %1;" : "=r"(u) : "f"(x)); return u;
}
__device__ __forceinline__ void split_tf32(float x, unsigned& hi, unsigned& lo) {
    hi = cvt_tf32(x);
    lo = cvt_tf32(x - __uint_as_float(hi));
}
__device__ __forceinline__ void mma8(float* c, const unsigned* a, const unsigned* b) {
    asm volatile(
        "mma.sync.aligned.m16n8k8.row.col.f32.tf32.tf32.f32 "
        "{%0,%1,%2,%3}, {%4,%5,%6,%7}, {%8,%9}, {%0,%1,%2,%3};"
        : "+f"(c[0]), "+f"(c[1]), "+f"(c[2]), "+f"(c[3])
        : "r"(a[0]), "r"(a[1]), "r"(a[2]), "r"(a[3]), "r"(b[0]), "r"(b[1]));
}
__device__ __forceinline__ void cp16(unsigned dst, const float* src) {
    asm volatile("cp.async.cg.shared.global [%0], [%1], 16;" :: "r"(dst), "l"(src));
}
#define CP_COMMIT() asm volatile("cp.async.commit_group;")
#define CP_WAIT1()  asm volatile("cp.async.wait_group 1;")
#define CP_WAIT0()  asm volatile("cp.async.wait_group 0;")

// ---------------- GEMM1: hdn = silu(X@wg[e]) * (X@wu[e]) ---------------------
// Block tile 128(M) x 64(N), KS=16, 2-stage cp.async pipeline, 3xTF32 mma.
// 8 warps: 4(M) x 2(N), warp tile 32x32 for BOTH G and U (shared A frags).
__global__ void __launch_bounds__(256) ffn1_kernel(
    const float* __restrict__ x,
    const float* __restrict__ wg,
    const float* __restrict__ wu) {
    const int e = blockIdx.z;
    const int cnt = g_counts[e];
    const int m0 = blockIdx.x * 128;          // m on x: consecutive blocks share B strip in L2
    if (m0 >= cnt) return;
    const int beg = g_offsets[e];
    const int n0 = blockIdx.y * 64;

    __shared__ float As[2][128][20];          // stride 20: bank = 4m+k (conflict-free frags)
    __shared__ float Bgs[2][16][72];          // stride 72: bank = 8k+n
    __shared__ float Bus[2][16][72];
    __shared__ int perm_s[128];

    const int tid = threadIdx.x;
    if (tid < 128) {
        int r = m0 + tid;
        perm_s[tid] = g_perm[beg + (r < cnt ? r : cnt - 1)];
    }
    __syncthreads();

    const float* wgb = wg + (size_t)e * H_DIM * I_DIM;
    const float* wub = wu + (size_t)e * H_DIM * I_DIM;

    // global->smem mappings
    const int ar = tid >> 2;            // A rows 0..63 (and +64)
    const int ac = (tid & 3) * 4;       // k col 0,4,8,12
    const float* axr0 = x + (size_t)perm_s[ar] * H_DIM + ac;
    const float* axr1 = x + (size_t)perm_s[ar + 64] * H_DIM + ac;
    const int bk = tid >> 4;            // 0..15
    const int bn = (tid & 15) * 4;      // 0..60

    unsigned As_u = (unsigned)__cvta_generic_to_shared(&As[0][0][0]);
    unsigned Bg_u = (unsigned)__cvta_generic_to_shared(&Bgs[0][0][0]);
    unsigned Bu_u = (unsigned)__cvta_generic_to_shared(&Bus[0][0][0]);
    const unsigned as_d0 = As_u + (ar * 20 + ac) * 4;
    const unsigned as_d1 = As_u + ((ar + 64) * 20 + ac) * 4;
    const unsigned bg_d  = Bg_u + (bk * 72 + bn) * 4;
    const unsigned bu_d  = Bu_u + (bk * 72 + bn) * 4;

    const int w = tid >> 5, lane = tid & 31;
    const int wm = (w >> 1) * 32, wn = (w & 1) * 32;
    const int fr = lane >> 2, fc = lane & 3;

    float accG[2][4][4] = {}, accU[2][4][4] = {};

    const int KT = H_DIM / 16;  // 64
    // prefetch stage 0
    cp16(as_d0, axr0);
    cp16(as_d1, axr1);
    cp16(bg_d, wgb + (size_t)bk * I_DIM + n0 + bn);
    cp16(bu_d, wub + (size_t)bk * I_DIM + n0 + bn);
    CP_COMMIT();

    for (int kt = 0; kt < KT; kt++) {
        if (kt + 1 < KT) {
            int k0 = (kt + 1) * 16;
            int st = (kt + 1) & 1;
            unsigned so = (unsigned)(st * 128 * 20 * 4);
            unsigned sb = (unsigned)(st * 16 * 72 * 4);
            cp16(as_d0 + so, axr0 + k0);
            cp16(as_d1 + so, axr1 + k0);
            cp16(bg_d + sb, wgb + (size_t)(k0 + bk) * I_DIM + n0 + bn);
            cp16(bu_d + sb, wub + (size_t)(k0 + bk) * I_DIM + n0 + bn);
            CP_COMMIT();
            CP_WAIT1();
        } else {
            CP_WAIT0();
        }
        __syncthreads();
        const int st = kt & 1;
        #pragma unroll
        for (int kk = 0; kk < 16; kk += 8) {
            unsigned Ah[2][4], Al[2][4];
            #pragma unroll
            for (int mi = 0; mi < 2; mi++) {
                int mb = wm + mi * 16 + fr;
                split_tf32(As[st][mb][kk + fc],         Ah[mi][0], Al[mi][0]);
                split_tf32(As[st][mb + 8][kk + fc],     Ah[mi][1], Al[mi][1]);
                split_tf32(As[st][mb][kk + fc + 4],     Ah[mi][2], Al[mi][2]);
                split_tf32(As[st][mb + 8][kk + fc + 4], Ah[mi][3], Al[mi][3]);
            }
            #pragma unroll
            for (int nj = 0; nj < 4; nj++) {
                int nb = wn + nj * 8 + fr;
                unsigned bh[2], bl[2];
                split_tf32(Bgs[st][kk + fc][nb],     bh[0], bl[0]);
                split_tf32(Bgs[st][kk + fc + 4][nb], bh[1], bl[1]);
                #pragma unroll
                for (int mi = 0; mi < 2; mi++) {
                    mma8(accG[mi][nj], Ah[mi], bh);
                    mma8(accG[mi][nj], Al[mi], bh);
                    mma8(accG[mi][nj], Ah[mi], bl);
                }
                split_tf32(Bus[st][kk + fc][nb],     bh[0], bl[0]);
                split_tf32(Bus[st][kk + fc + 4][nb], bh[1], bl[1]);
                #pragma unroll
                for (int mi = 0; mi < 2; mi++) {
                    mma8(accU[mi][nj], Ah[mi], bh);
                    mma8(accU[mi][nj], Al[mi], bh);
                    mma8(accU[mi][nj], Ah[mi], bl);
                }
            }
        }
        __syncthreads();
    }

    // epilogue: silu(g)*u
    #pragma unroll
    for (int mi = 0; mi < 2; mi++) {
        #pragma unroll
        for (int nj = 0; nj < 4; nj++) {
            int row = m0 + wm + mi * 16 + fr;
            int col = n0 + wn + nj * 8 + 2 * fc;
            if (row < cnt) {
                float g0 = accG[mi][nj][0], g1 = accG[mi][nj][1];
                float u0 = accU[mi][nj][0], u1 = accU[mi][nj][1];
                float2 v;
                v.x = g0 / (1.f + expf(-g0)) * u0;
                v.y = g1 / (1.f + expf(-g1)) * u1;
                *(float2*)&g_hdn[(size_t)(beg + row) * I_DIM + col] = v;
            }
            if (row + 8 < cnt) {
                float g0 = accG[mi][nj][2], g1 = accG[mi][nj][3];
                float u0 = accU[mi][nj][2], u1 = accU[mi][nj][3];
                float2 v;
                v.x = g0 / (1.f + expf(-g0)) * u0;
                v.y = g1 / (1.f + expf(-g1)) * u1;
                *(float2*)&g_hdn[(size_t)(beg + row + 8) * I_DIM + col] = v;
            }
        }
    }
}

// ---------------- GEMM2: pairout = (hdn @ wd[e]) * pairw ---------------------
// Block tile 128(M) x 128(N), KS=16. 8 warps: 4(M) x 2(N), warp tile 32x64.
__global__ void __launch_bounds__(256) ffn2_kernel(const float* __restrict__ wd) {
    const int e = blockIdx.z;
    const int cnt = g_counts[e];
    const int m0 = blockIdx.x * 128;
    if (m0 >= cnt) return;
    const int beg = g_offsets[e];
    const int n0 = blockIdx.y * 128;

    __shared__ float As[2][128][20];
    __shared__ float Bs[2][16][136];   // stride 136: bank = 8k+n

    const int tid = threadIdx.x;
    const float* wdb = wd + (size_t)e * I_DIM * H_DIM;

    const int ar = tid >> 2;
    const int ac = (tid & 3) * 4;
    int r0 = m0 + ar;       if (r0 >= cnt) r0 = cnt - 1;
    int r1 = m0 + ar + 64;  if (r1 >= cnt) r1 = cnt - 1;
    const float* axr0 = g_hdn + (size_t)(beg + r0) * I_DIM + ac;
    const float* axr1 = g_hdn + (size_t)(beg + r1) * I_DIM + ac;
    const int bk = tid >> 5;            // 0..7 (and +8)
    const int bn = (tid & 31) * 4;      // 0..124

    unsigned As_u = (unsigned)__cvta_generic_to_shared(&As[0][0][0]);
    unsigned Bs_u = (unsigned)__cvta_generic_to_shared(&Bs[0][0][0]);
    const unsigned as_d0 = As_u + (ar * 20 + ac) * 4;
    const unsigned as_d1 = As_u + ((ar + 64) * 20 + ac) * 4;
    const unsigned bs_d0 = Bs_u + (bk * 136 + bn) * 4;
    const unsigned bs_d1 = Bs_u + ((bk + 8) * 136 + bn) * 4;

    const int w = tid >> 5, lane = tid & 31;
    const int wm = (w >> 1) * 32, wn = (w & 1) * 64;
    const int fr = lane >> 2, fc = lane & 3;

    float acc[2][8][4] = {};

    const int KT = I_DIM / 16;  // 256
    cp16(as_d0, axr0);
    cp16(as_d1, axr1);
    cp16(bs_d0, wdb + (size_t)bk * H_DIM + n0 + bn);
    cp16(bs_d1, wdb + (size_t)(bk + 8) * H_DIM + n0 + bn);
    CP_COMMIT();

    for (int kt = 0; kt < KT; kt++) {
        if (kt + 1 < KT) {
            int k0 = (kt + 1) * 16;
            int st = (kt + 1) & 1;
            unsigned so = (unsigned)(st * 128 * 20 * 4);
            unsigned sb = (unsigned)(st * 16 * 136 * 4);
            cp16(as_d0 + so, axr0 + k0);
            cp16(as_d1 + so, axr1 + k0);
            cp16(bs_d0 + sb, wdb + (size_t)(k0 + bk) * H_DIM + n0 + bn);
            cp16(bs_d1 + sb, wdb + (size_t)(k0 + bk + 8) * H_DIM + n0 + bn);
            CP_COMMIT();
            CP_WAIT1();
        } else {
            CP_WAIT0();
        }
        __syncthreads();
        const int st = kt & 1;
        #pragma unroll
        for (int kk = 0; kk < 16; kk += 8) {
            unsigned Ah[2][4], Al[2][4];
            #pragma unroll
            for (int mi = 0; mi < 2; mi++) {
                int mb = wm + mi * 16 + fr;
                split_tf32(As[st][mb][kk + fc],         Ah[mi][0], Al[mi][0]);
                split_tf32(As[st][mb + 8][kk + fc],     Ah[mi][1], Al[mi][1]);
                split_tf32(As[st][mb][kk + fc + 4],     Ah[mi][2], Al[mi][2]);
                split_tf32(As[st][mb + 8][kk + fc + 4], Ah[mi][3], Al[mi][3]);
            }
            #pragma unroll
            for (int nj = 0; nj < 8; nj++) {
                int nb = wn + nj * 8 + fr;
                unsigned bh[2], bl[2];
                split_tf32(Bs[st][kk + fc][nb],     bh[0], bl[0]);
                split_tf32(Bs[st][kk + fc + 4][nb], bh[1], bl[1]);
                #pragma unroll
                for (int mi = 0; mi < 2; mi++) {
                    mma8(acc[mi][nj], Ah[mi], bh);
                    mma8(acc[mi][nj], Al[mi], bh);
                    mma8(acc[mi][nj], Ah[mi], bl);
                }
            }
        }
        __syncthreads();
    }

    #pragma unroll
    for (int mi = 0; mi < 2; mi++) {
        int row = m0 + wm + mi * 16 + fr;
        float pw0 = (row < cnt)     ? g_pairw[beg + row]     : 0.f;
        float pw8 = (row + 8 < cnt) ? g_pairw[beg + row + 8] : 0.f;
        #pragma unroll
        for (int nj = 0; nj < 8; nj++) {
            int col = n0 + wn + nj * 8 + 2 * fc;
            if (row < cnt) {
                float2 v = { acc[mi][nj][0] * pw0, acc[mi][nj][1] * pw0 };
                *(float2*)&g_pairout[(size_t)(beg + row) * H_DIM + col] = v;
            }
            if (row + 8 < cnt) {
                float2 v = { acc[mi][nj][2] * pw8, acc[mi][nj][3] * pw8 };
                *(float2*)&g_pairout[(size_t)(beg + row + 8) * H_DIM + col] = v;
            }
        }
    }
}

// ---------------- combine: out[t] = pairout[pos0] + pairout[pos1] ------------
__global__ void combine_kernel(float* __restrict__ out) {
    int idx = blockIdx.x * blockDim.x + threadIdx.x;
    if (idx >= T_TOK * H_DIM) return;
    int t = idx >> 10;
    int h = idx & (H_DIM - 1);
    int p0 = g_pos[t * 2 + 0], p1 = g_pos[t * 2 + 1];
    out[idx] = g_pairout[(size_t)p0 * H_DIM + h] + g_pairout[(size_t)p1 * H_DIM + h];
}

// ---------------- launcher ----------------------------------------------------
extern "C" void kernel_launch(void* const* d_in, const int* in_sizes, int n_in,
                              void* d_out, int out_size) {
    const float* x  = (const float*)d_in[0];
    const float* gw = (const float*)d_in[1];
    const float* wg = (const float*)d_in[2];
    const float* wu = (const float*)d_in[3];
    const float* wd = (const float*)d_in[4];
    float* out = (float*)d_out;

    zero_kernel<<<1, 32>>>();
    router_kernel<<<T_TOK, 256>>>(x, gw);
    int write_aux = (out_size > T_TOK * H_DIM) ? 1 : 0;
    finalize_router<<<1, 1>>>(out + (size_t)T_TOK * H_DIM, write_aux);
    scatter_kernel<<<(T_TOK + 255) / 256, 256>>>();

    // m-tiles on x so consecutive blocks share the same weight strip in L2
    dim3 g1(32, I_DIM / 64, E_EXP);    // (m-tiles max 4096/128, n-tiles, experts)
    ffn1_kernel<<<g1, 256>>>(x, wg, wu);
    dim3 g2(32, H_DIM / 128, E_EXP);
    ffn2_kernel<<<g2, 256>>>(wd);

    combine_kernel<<<(T_TOK * H_DIM + 255) / 256, 256>>>(out);
}